// round 1
// baseline (speedup 1.0000x reference)
#include <cuda_runtime.h>
#include <cstdint>

// ----------------------------------------------------------------------------
// SVDLinearAddition: y = x @ ((U * (S+eps)) @ Vt)^T + bias
//   x  : [M=8192, K=4096]  (B*T flattened)
//   U  : [4096, 4096], S/eps: [4096], Vt: [4096, 4096], bias: [4096]
// Plan: GEMM1 w[o,k] = sum_r (U[o,r]*(S[r]+eps[r])) * Vt[r,k]   (NN, 137 GF)
//       GEMM2 y[m,o] = sum_k x[m,k] * w[o,k] + bias[o]          (NT, 275 GF)
// Scratch w lives in a __device__ global (no allocations allowed).
// ----------------------------------------------------------------------------

#define BM 128
#define BN 128
#define BK 16
#define TM 8
#define TN 8
#define THREADS 256

// 4096*4096 fp32 scratch for w (64 MB, static device global: allowed)
__device__ float g_w[4096ull * 4096ull];

// ---------------------------------------------------------------------------
// GEMM1: C = (A * s) @ B   (A=U [M,K] row-major, B=Vt [K,N] row-major)
// scale s[r] applied to B rows (equivalent to scaling U columns).
// C = g_w [M,N] row-major.
// ---------------------------------------------------------------------------
__global__ __launch_bounds__(THREADS, 2)
void svd_gemm1(const float* __restrict__ U,
               const float* __restrict__ Vt,
               const float* __restrict__ S,
               const float* __restrict__ eps,
               int M, int N, int K)
{
    __shared__ float As[BK][BM];
    __shared__ float Bs[BK][BN];

    const int tid = threadIdx.x;
    const int tx  = tid & 15;   // 16 thread cols
    const int ty  = tid >> 4;   // 16 thread rows
    const int m0  = blockIdx.y * BM;
    const int n0  = blockIdx.x * BN;

    float acc[TM][TN] = {};

    for (int kt = 0; kt < K; kt += BK) {
        // --- load A tile [BM x BK], store transposed As[k][m] ---
        #pragma unroll
        for (int t = 0; t < 2; t++) {
            int i   = tid + t * THREADS;     // 0..511 (512 float4 = 128*16)
            int row = i >> 2;                // BK/4 = 4 float4 per row
            int kq  = (i & 3) << 2;
            float4 v = *reinterpret_cast<const float4*>(
                U + (size_t)(m0 + row) * K + kt + kq);
            As[kq + 0][row] = v.x;
            As[kq + 1][row] = v.y;
            As[kq + 2][row] = v.z;
            As[kq + 3][row] = v.w;
        }
        // --- load B tile [BK x BN] direct (row-major), scale by s[r] ---
        #pragma unroll
        for (int t = 0; t < 2; t++) {
            int i  = tid + t * THREADS;
            int rr = i >> 5;                 // BN/4 = 32 float4 per row
            int c  = (i & 31) << 2;
            float s = S[kt + rr] + eps[kt + rr];
            float4 v = *reinterpret_cast<const float4*>(
                Vt + (size_t)(kt + rr) * N + n0 + c);
            Bs[rr][c + 0] = v.x * s;
            Bs[rr][c + 1] = v.y * s;
            Bs[rr][c + 2] = v.z * s;
            Bs[rr][c + 3] = v.w * s;
        }
        __syncthreads();

        #pragma unroll
        for (int kk = 0; kk < BK; kk++) {
            float a[TM], b[TN];
            *reinterpret_cast<float4*>(a)     = *reinterpret_cast<const float4*>(&As[kk][ty * TM]);
            *reinterpret_cast<float4*>(a + 4) = *reinterpret_cast<const float4*>(&As[kk][ty * TM + 4]);
            *reinterpret_cast<float4*>(b)     = *reinterpret_cast<const float4*>(&Bs[kk][tx * TN]);
            *reinterpret_cast<float4*>(b + 4) = *reinterpret_cast<const float4*>(&Bs[kk][tx * TN + 4]);
            #pragma unroll
            for (int i = 0; i < TM; i++)
                #pragma unroll
                for (int j = 0; j < TN; j++)
                    acc[i][j] = fmaf(a[i], b[j], acc[i][j]);
        }
        __syncthreads();
    }

    #pragma unroll
    for (int i = 0; i < TM; i++) {
        size_t row = (size_t)(m0 + ty * TM + i);
        float4* out = reinterpret_cast<float4*>(g_w + row * N + n0 + tx * TN);
        out[0] = make_float4(acc[i][0], acc[i][1], acc[i][2], acc[i][3]);
        out[1] = make_float4(acc[i][4], acc[i][5], acc[i][6], acc[i][7]);
    }
}

// ---------------------------------------------------------------------------
// GEMM2 (NT): Y[m,n] = sum_k X[m,k] * W[n,k] + bias[n]
// X [M,K] row-major, W = g_w [N,K] row-major, Y [M,N] row-major.
// ---------------------------------------------------------------------------
__global__ __launch_bounds__(THREADS, 2)
void svd_gemm2(const float* __restrict__ X,
               const float* __restrict__ bias,
               float* __restrict__ Y,
               int M, int N, int K)
{
    __shared__ float As[BK][BM];
    __shared__ float Bs[BK][BN];

    const int tid = threadIdx.x;
    const int tx  = tid & 15;
    const int ty  = tid >> 4;
    const int m0  = blockIdx.y * BM;
    const int n0  = blockIdx.x * BN;

    float acc[TM][TN] = {};

    for (int kt = 0; kt < K; kt += BK) {
        // --- load A tile (X), transposed scatter into As[k][m] ---
        #pragma unroll
        for (int t = 0; t < 2; t++) {
            int i   = tid + t * THREADS;
            int row = i >> 2;
            int kq  = (i & 3) << 2;
            float4 v = *reinterpret_cast<const float4*>(
                X + (size_t)(m0 + row) * K + kt + kq);
            As[kq + 0][row] = v.x;
            As[kq + 1][row] = v.y;
            As[kq + 2][row] = v.z;
            As[kq + 3][row] = v.w;
        }
        // --- load B tile (W, K-major rows), transposed scatter Bs[k][n] ---
        #pragma unroll
        for (int t = 0; t < 2; t++) {
            int i  = tid + t * THREADS;
            int n  = i >> 2;
            int kq = (i & 3) << 2;
            float4 v = *reinterpret_cast<const float4*>(
                g_w + (size_t)(n0 + n) * K + kt + kq);
            Bs[kq + 0][n] = v.x;
            Bs[kq + 1][n] = v.y;
            Bs[kq + 2][n] = v.z;
            Bs[kq + 3][n] = v.w;
        }
        __syncthreads();

        #pragma unroll
        for (int kk = 0; kk < BK; kk++) {
            float a[TM], b[TN];
            *reinterpret_cast<float4*>(a)     = *reinterpret_cast<const float4*>(&As[kk][ty * TM]);
            *reinterpret_cast<float4*>(a + 4) = *reinterpret_cast<const float4*>(&As[kk][ty * TM + 4]);
            *reinterpret_cast<float4*>(b)     = *reinterpret_cast<const float4*>(&Bs[kk][tx * TN]);
            *reinterpret_cast<float4*>(b + 4) = *reinterpret_cast<const float4*>(&Bs[kk][tx * TN + 4]);
            #pragma unroll
            for (int i = 0; i < TM; i++)
                #pragma unroll
                for (int j = 0; j < TN; j++)
                    acc[i][j] = fmaf(a[i], b[j], acc[i][j]);
        }
        __syncthreads();
    }

    const int nb = n0 + tx * TN;
    float bv[TN];
    #pragma unroll
    for (int j = 0; j < TN; j++) bv[j] = bias[nb + j];

    #pragma unroll
    for (int i = 0; i < TM; i++) {
        size_t row = (size_t)(m0 + ty * TM + i);
        float4* out = reinterpret_cast<float4*>(Y + row * N + nb);
        out[0] = make_float4(acc[i][0] + bv[0], acc[i][1] + bv[1],
                             acc[i][2] + bv[2], acc[i][3] + bv[3]);
        out[1] = make_float4(acc[i][4] + bv[4], acc[i][5] + bv[5],
                             acc[i][6] + bv[6], acc[i][7] + bv[7]);
    }
}

// ---------------------------------------------------------------------------
// Harness entry. Input order (metadata): x, U, S, Vt, epsilon, bias.
// ---------------------------------------------------------------------------
extern "C" void kernel_launch(void* const* d_in, const int* in_sizes, int n_in,
                              void* d_out, int out_size)
{
    const float* x    = (const float*)d_in[0];
    const float* U    = (const float*)d_in[1];
    const float* S    = (const float*)d_in[2];
    const float* Vt   = (const float*)d_in[3];
    const float* eps  = (const float*)d_in[4];
    const float* bias = (const float*)d_in[5];
    float* y = (float*)d_out;

    const int r     = in_sizes[2];           // 4096
    const int dIn   = in_sizes[3] / r;       // 4096
    const int dOut  = in_sizes[1] / r;       // 4096
    const int M     = in_sizes[0] / dIn;     // 8192 (B*T)

    // GEMM1: w[dOut, dIn] = (U * (S+eps)) @ Vt
    {
        dim3 grid(dIn / BN, dOut / BM);
        svd_gemm1<<<grid, THREADS>>>(U, Vt, S, eps, dOut, dIn, r);
    }
    // GEMM2: y[M, dOut] = x @ w^T + bias
    {
        dim3 grid(dOut / BN, M / BM);
        svd_gemm2<<<grid, THREADS>>>(x, bias, y, M, dOut, dIn);
    }
}

// round 3
// speedup vs baseline: 2.5736x; 2.5736x over previous
#include <cuda_runtime.h>
#include <cuda_bf16.h>
#include <cstdint>

// =============================================================================
// SVDLinearAddition via mma.sync bf16x3 (2-way hi/lo split, 3 MMA products):
//   GEMM1: w[o,k] = sum_r (U[o,r]*(S[r]+eps[r])) * Vt[r,k]   -> g_w scratch
//   GEMM2: y[m,o] = sum_k x[m,k] * w[o,k] + bias[o]
// tcgen05 is unavailable (harness PTX target = compute_100, no 'a' suffix),
// so we use ldmatrix + mma.sync.m16n8k16 (sm_80+) on the tensor pipe.
// =============================================================================

__device__ float g_w[4096ull * 4096ull];   // 64MB scratch (device global: legal)

// ---------------------------- helpers ---------------------------------------
static __device__ __forceinline__ uint32_t smem_u32(const void* p) {
    uint32_t a;
    asm("{ .reg .u64 t; cvta.to.shared.u64 t, %1; cvt.u32.u64 %0, t; }"
        : "=r"(a) : "l"(p));
    return a;
}
static __device__ __forceinline__ uint32_t sw128(uint32_t o) {
    return o ^ ((o >> 3) & 0x70);
}
static __device__ __forceinline__ void ldsm4(uint32_t& r0, uint32_t& r1,
                                             uint32_t& r2, uint32_t& r3, uint32_t a) {
    asm volatile("ldmatrix.sync.aligned.m8n8.x4.shared.b16 {%0,%1,%2,%3}, [%4];"
                 : "=r"(r0), "=r"(r1), "=r"(r2), "=r"(r3) : "r"(a));
}
static __device__ __forceinline__ void mma16816(float& c0, float& c1, float& c2, float& c3,
                                                uint32_t a0, uint32_t a1, uint32_t a2, uint32_t a3,
                                                uint32_t b0, uint32_t b1) {
    asm volatile(
        "mma.sync.aligned.m16n8k16.row.col.f32.bf16.bf16.f32 "
        "{%0,%1,%2,%3}, {%4,%5,%6,%7}, {%8,%9}, {%0,%1,%2,%3};"
        : "+f"(c0), "+f"(c1), "+f"(c2), "+f"(c3)
        : "r"(a0), "r"(a1), "r"(a2), "r"(a3), "r"(b0), "r"(b1));
}
// fp32x4 -> hi/lo bf16x4 split, packed as uint2 each (k-contiguous)
static __device__ __forceinline__ void split4(float4 v, uint2& hi, uint2& lo) {
    __nv_bfloat162 h01 = __floats2bfloat162_rn(v.x, v.y);
    __nv_bfloat162 h23 = __floats2bfloat162_rn(v.z, v.w);
    float r0 = v.x - __bfloat162float(h01.x);
    float r1 = v.y - __bfloat162float(h01.y);
    float r2 = v.z - __bfloat162float(h23.x);
    float r3 = v.w - __bfloat162float(h23.y);
    __nv_bfloat162 l01 = __floats2bfloat162_rn(r0, r1);
    __nv_bfloat162 l23 = __floats2bfloat162_rn(r2, r3);
    hi.x = *reinterpret_cast<uint32_t*>(&h01);
    hi.y = *reinterpret_cast<uint32_t*>(&h23);
    lo.x = *reinterpret_cast<uint32_t*>(&l01);
    lo.y = *reinterpret_cast<uint32_t*>(&l23);
}

// Tiling: CTA 128x128, Kc = 64 bf16 (rows of 128B, SW128 swizzle).
// smem per stage: A_hi/A_lo/B_hi/B_lo, 16KB each = 64KB; 2 stages.
#define KC 64
#define T_AHI 0
#define T_ALO 16384
#define T_BHI 32768
#define T_BLO 49152
#define STAGE 65536
#define SMEM_BYTES (2 * STAGE + 1024)

// Shared MMA core: given smem tile bases for current stage, run 4 k16 steps.
// Warp layout: 2(m) x 4(n) warps; warp tile 64x32.
#define MMA_CORE(stage_base)                                                         \
    {                                                                                \
        const uint32_t Ah = (stage_base) + T_AHI;                                    \
        const uint32_t Al = (stage_base) + T_ALO;                                    \
        const uint32_t Bh = (stage_base) + T_BHI;                                    \
        const uint32_t Bl = (stage_base) + T_BLO;                                    \
        _Pragma("unroll")                                                            \
        for (int kk = 0; kk < 4; kk++) {                                             \
            uint32_t ah[4][4], al[4][4], bh[2][4], bl[2][4];                         \
            _Pragma("unroll")                                                        \
            for (int mi = 0; mi < 4; mi++) {                                         \
                uint32_t off = sw128((rowA + mi * 16) * 128 + kk * 32 + colA);       \
                ldsm4(ah[mi][0], ah[mi][1], ah[mi][2], ah[mi][3], Ah + off);         \
                ldsm4(al[mi][0], al[mi][1], al[mi][2], al[mi][3], Al + off);         \
            }                                                                        \
            _Pragma("unroll")                                                        \
            for (int p = 0; p < 2; p++) {                                            \
                uint32_t off = sw128((rowB + p * 16) * 128 + kk * 32 + colB);        \
                ldsm4(bh[p][0], bh[p][1], bh[p][2], bh[p][3], Bh + off);             \
                ldsm4(bl[p][0], bl[p][1], bl[p][2], bl[p][3], Bl + off);             \
            }                                                                        \
            _Pragma("unroll")                                                        \
            for (int mi = 0; mi < 4; mi++) {                                         \
                _Pragma("unroll")                                                    \
                for (int ni = 0; ni < 4; ni++) {                                     \
                    uint32_t vb0 = bh[ni >> 1][(ni & 1) * 2];                        \
                    uint32_t vb1 = bh[ni >> 1][(ni & 1) * 2 + 1];                    \
                    uint32_t wb0 = bl[ni >> 1][(ni & 1) * 2];                        \
                    uint32_t wb1 = bl[ni >> 1][(ni & 1) * 2 + 1];                    \
                    float* c = acc[mi][ni];                                          \
                    mma16816(c[0], c[1], c[2], c[3],                                 \
                             ah[mi][0], ah[mi][1], ah[mi][2], ah[mi][3], vb0, vb1);  \
                    mma16816(c[0], c[1], c[2], c[3],                                 \
                             ah[mi][0], ah[mi][1], ah[mi][2], ah[mi][3], wb0, wb1);  \
                    mma16816(c[0], c[1], c[2], c[3],                                 \
                             al[mi][0], al[mi][1], al[mi][2], al[mi][3], vb0, vb1);  \
                }                                                                    \
            }                                                                        \
        }                                                                            \
    }

// =============================================================================
// GEMM2 (NT): Y[m,n] = sum_k X[m,k] * W[n,k] + bias[n]
// A = X rows (K-major), B = g_w rows (K-major). Both plain ldmatrix.
// =============================================================================
__global__ __launch_bounds__(256, 1)
void mm_gemm2(const float* __restrict__ X, const float* __restrict__ bias,
              float* __restrict__ Y, int M, int N, int K)
{
    extern __shared__ char smem[];
    const uint32_t sb = smem_u32(smem);
    const uint32_t data0 = (sb + 1023) & ~1023u;

    const int tid = threadIdx.x;
    const int wid = tid >> 5, lane = tid & 31;
    const int m0 = blockIdx.y * 128;
    const int n0 = blockIdx.x * 128;
    const int mw = (wid & 1) * 64;
    const int nw = (wid >> 1) * 32;

    // ldmatrix per-thread row/col components
    const uint32_t rowA = mw + (lane & 7) + ((lane >> 3) & 1) * 8;
    const uint32_t colA = ((lane >> 4) & 1) * 16;
    const uint32_t rowB = nw + (lane & 7) + ((lane >> 4) & 1) * 8;
    const uint32_t colB = ((lane >> 3) & 1) * 16;

    // global load pattern: fixed q-column per thread, 8 rows each (A and B)
    const int lq = tid & 15;          // float4 index within 64-float row
    const int lr = tid >> 4;          // base row (0..15), step 16

    float acc[4][4][4];
    #pragma unroll
    for (int i = 0; i < 4; i++)
        #pragma unroll
        for (int j = 0; j < 4; j++)
            #pragma unroll
            for (int q = 0; q < 4; q++) acc[i][j][q] = 0.f;

    const int KI = K / KC;
    float4 va[8], vb[8];

    // prologue: load k-tile 0 and store stage 0
    #pragma unroll
    for (int i = 0; i < 8; i++) {
        int row = lr + i * 16;
        va[i] = *reinterpret_cast<const float4*>(X   + (size_t)(m0 + row) * K + lq * 4);
        vb[i] = *reinterpret_cast<const float4*>(g_w + (size_t)(n0 + row) * K + lq * 4);
    }
    {
        uint32_t s0 = data0;
        #pragma unroll
        for (int i = 0; i < 8; i++) {
            int row = lr + i * 16;
            uint32_t off = sw128((uint32_t)(row * 128 + lq * 8));
            uint2 hu, lu;
            split4(va[i], hu, lu);
            *reinterpret_cast<uint2*>(smem + (s0 - sb) + T_AHI + off) = hu;
            *reinterpret_cast<uint2*>(smem + (s0 - sb) + T_ALO + off) = lu;
            split4(vb[i], hu, lu);
            *reinterpret_cast<uint2*>(smem + (s0 - sb) + T_BHI + off) = hu;
            *reinterpret_cast<uint2*>(smem + (s0 - sb) + T_BLO + off) = lu;
        }
    }
    __syncthreads();

    for (int kt = 0; kt < KI; kt++) {
        const int nx = kt + 1;
        if (nx < KI) {
            const int k0 = nx * KC;
            #pragma unroll
            for (int i = 0; i < 8; i++) {
                int row = lr + i * 16;
                va[i] = *reinterpret_cast<const float4*>(X   + (size_t)(m0 + row) * K + k0 + lq * 4);
                vb[i] = *reinterpret_cast<const float4*>(g_w + (size_t)(n0 + row) * K + k0 + lq * 4);
            }
        }

        MMA_CORE(data0 + (uint32_t)(kt & 1) * STAGE);

        if (nx < KI) {
            uint32_t sN = data0 + (uint32_t)(nx & 1) * STAGE;
            #pragma unroll
            for (int i = 0; i < 8; i++) {
                int row = lr + i * 16;
                uint32_t off = sw128((uint32_t)(row * 128 + lq * 8));
                uint2 hu, lu;
                split4(va[i], hu, lu);
                *reinterpret_cast<uint2*>(smem + (sN - sb) + T_AHI + off) = hu;
                *reinterpret_cast<uint2*>(smem + (sN - sb) + T_ALO + off) = lu;
                split4(vb[i], hu, lu);
                *reinterpret_cast<uint2*>(smem + (sN - sb) + T_BHI + off) = hu;
                *reinterpret_cast<uint2*>(smem + (sN - sb) + T_BLO + off) = lu;
            }
            __syncthreads();
        }
    }

    // epilogue with bias
    const int erow = lane >> 2;
    const int ecol = (lane & 3) * 2;
    #pragma unroll
    for (int ni = 0; ni < 4; ni++) {
        int n = n0 + nw + ni * 8 + ecol;
        float2 bv = *reinterpret_cast<const float2*>(bias + n);
        #pragma unroll
        for (int mi = 0; mi < 4; mi++) {
            int m = m0 + mw + mi * 16 + erow;
            float* c = acc[mi][ni];
            *reinterpret_cast<float2*>(Y + (size_t)m * N + n) =
                make_float2(c[0] + bv.x, c[1] + bv.y);
            *reinterpret_cast<float2*>(Y + (size_t)(m + 8) * N + n) =
                make_float2(c[2] + bv.x, c[3] + bv.y);
        }
    }
}

// =============================================================================
// GEMM1 (NN): W[o,k] = sum_r (U[o,r]*(S[r]+eps[r])) * Vt[r,k]
// A = U rows (K-major, scaled on load); B[n][k] = Vt[k][n] gathered transpose.
// =============================================================================
__global__ __launch_bounds__(256, 1)
void mm_gemm1(const float* __restrict__ U, const float* __restrict__ Vt,
              const float* __restrict__ S, const float* __restrict__ eps,
              int dOut, int dIn, int R)
{
    extern __shared__ char smem[];
    const uint32_t sb = smem_u32(smem);
    const uint32_t data0 = (sb + 1023) & ~1023u;

    const int tid = threadIdx.x;
    const int wid = tid >> 5, lane = tid & 31;
    const int m0 = blockIdx.y * 128;   // dOut
    const int n0 = blockIdx.x * 128;   // dIn
    const int mw = (wid & 1) * 64;
    const int nw = (wid >> 1) * 32;

    const uint32_t rowA = mw + (lane & 7) + ((lane >> 3) & 1) * 8;
    const uint32_t colA = ((lane >> 4) & 1) * 16;
    const uint32_t rowB = nw + (lane & 7) + ((lane >> 4) & 1) * 8;
    const uint32_t colB = ((lane >> 3) & 1) * 16;

    const int lq = tid & 15;
    const int lr = tid >> 4;
    // B gather pattern: n fixed per thread, k-groups of 4
    const int gn = tid & 127;
    const int gk = (tid >> 7) * 4;    // 0 or 4

    float acc[4][4][4];
    #pragma unroll
    for (int i = 0; i < 4; i++)
        #pragma unroll
        for (int j = 0; j < 4; j++)
            #pragma unroll
            for (int q = 0; q < 4; q++) acc[i][j][q] = 0.f;

    const int KI = R / KC;
    float4 va[8];
    float fb[8][4];
    float4 sc;

    // ---- stage loaders -------------------------------------------------------
    auto LOAD = [&](int kt) {
        const int k0 = kt * KC;
        float4 sv = *reinterpret_cast<const float4*>(S   + k0 + lq * 4);
        float4 ev = *reinterpret_cast<const float4*>(eps + k0 + lq * 4);
        sc = make_float4(sv.x + ev.x, sv.y + ev.y, sv.z + ev.z, sv.w + ev.w);
        #pragma unroll
        for (int i = 0; i < 8; i++) {
            int row = lr + i * 16;
            va[i] = *reinterpret_cast<const float4*>(U + (size_t)(m0 + row) * R + k0 + lq * 4);
        }
        #pragma unroll
        for (int g = 0; g < 8; g++) {
            int k = g * 8 + gk;
            const float* p = Vt + (size_t)(k0 + k) * dIn + n0 + gn;
            fb[g][0] = p[0];
            fb[g][1] = p[(size_t)dIn];
            fb[g][2] = p[2 * (size_t)dIn];
            fb[g][3] = p[3 * (size_t)dIn];
        }
    };
    auto STORE = [&](uint32_t sBase) {
        #pragma unroll
        for (int i = 0; i < 8; i++) {
            int row = lr + i * 16;
            float4 w = va[i];
            w.x *= sc.x; w.y *= sc.y; w.z *= sc.z; w.w *= sc.w;
            uint2 hu, lu;
            split4(w, hu, lu);
            uint32_t off = sw128((uint32_t)(row * 128 + lq * 8));
            *reinterpret_cast<uint2*>(smem + (sBase - sb) + T_AHI + off) = hu;
            *reinterpret_cast<uint2*>(smem + (sBase - sb) + T_ALO + off) = lu;
        }
        #pragma unroll
        for (int g = 0; g < 8; g++) {
            int k = g * 8 + gk;
            uint2 hu, lu;
            split4(make_float4(fb[g][0], fb[g][1], fb[g][2], fb[g][3]), hu, lu);
            uint32_t off = sw128((uint32_t)(gn * 128 + k * 2));
            *reinterpret_cast<uint2*>(smem + (sBase - sb) + T_BHI + off) = hu;
            *reinterpret_cast<uint2*>(smem + (sBase - sb) + T_BLO + off) = lu;
        }
    };

    LOAD(0);
    STORE(data0);
    __syncthreads();

    for (int kt = 0; kt < KI; kt++) {
        const int nx = kt + 1;
        if (nx < KI) LOAD(nx);

        MMA_CORE(data0 + (uint32_t)(kt & 1) * STAGE);

        if (nx < KI) {
            STORE(data0 + (uint32_t)(nx & 1) * STAGE);
            __syncthreads();
        }
    }

    // epilogue -> g_w
    const int erow = lane >> 2;
    const int ecol = (lane & 3) * 2;
    #pragma unroll
    for (int ni = 0; ni < 4; ni++) {
        int n = n0 + nw + ni * 8 + ecol;
        #pragma unroll
        for (int mi = 0; mi < 4; mi++) {
            int m = m0 + mw + mi * 16 + erow;
            float* c = acc[mi][ni];
            *reinterpret_cast<float2*>(g_w + (size_t)m * dIn + n) = make_float2(c[0], c[1]);
            *reinterpret_cast<float2*>(g_w + (size_t)(m + 8) * dIn + n) = make_float2(c[2], c[3]);
        }
    }
}

// =============================================================================
// Entry. Inputs: x, U, S, Vt, epsilon, bias
// =============================================================================
extern "C" void kernel_launch(void* const* d_in, const int* in_sizes, int n_in,
                              void* d_out, int out_size)
{
    const float* x    = (const float*)d_in[0];
    const float* U    = (const float*)d_in[1];
    const float* S    = (const float*)d_in[2];
    const float* Vt   = (const float*)d_in[3];
    const float* eps  = (const float*)d_in[4];
    const float* bias = (const float*)d_in[5];
    float* y = (float*)d_out;

    const int r    = in_sizes[2];          // 4096
    const int dIn  = in_sizes[3] / r;      // 4096
    const int dOut = in_sizes[1] / r;      // 4096
    const int M    = in_sizes[0] / dIn;    // 8192

    static bool attr_done = false;
    if (!attr_done) {
        cudaFuncSetAttribute(mm_gemm1, cudaFuncAttributeMaxDynamicSharedMemorySize, SMEM_BYTES);
        cudaFuncSetAttribute(mm_gemm2, cudaFuncAttributeMaxDynamicSharedMemorySize, SMEM_BYTES);
        attr_done = true;
    }

    {
        dim3 grid(dIn / 128, dOut / 128);
        mm_gemm1<<<grid, 256, SMEM_BYTES>>>(U, Vt, S, eps, dOut, dIn, r);
    }
    {
        dim3 grid(dOut / 128, M / 128);
        mm_gemm2<<<grid, 256, SMEM_BYTES>>>(x, bias, y, M, dOut, dIn);
    }
}

// round 4
// speedup vs baseline: 3.1237x; 1.2138x over previous
#include <cuda_runtime.h>
#include <cuda_bf16.h>
#include <cstdint>

// =============================================================================
// SVDLinearAddition, bf16x3 split-precision on mma.sync (tensor pipe):
//   prep:  xh/xl = split(x); uh/ul = split(U*(S+eps)); vh/vl = split(Vt^T)
//   GEMM1: w = u @ v^T   (split epilogue -> wh/wl bf16)
//   GEMM2: y = x @ w^T + bias (fp32 epilogue)
// All hot-loop operands pre-converted bf16; cp.async staging; 128x256 CTA tile.
// =============================================================================

__device__ uint16_t g_xh[8192ull * 4096], g_xl[8192ull * 4096];
__device__ uint16_t g_uh[4096ull * 4096], g_ul[4096ull * 4096];
__device__ uint16_t g_vh[4096ull * 4096], g_vl[4096ull * 4096];
__device__ uint16_t g_wh[4096ull * 4096], g_wl[4096ull * 4096];

// ---------------------------- helpers ---------------------------------------
static __device__ __forceinline__ uint32_t smem_u32(const void* p) {
    uint32_t a;
    asm("{ .reg .u64 t; cvta.to.shared.u64 t, %1; cvt.u32.u64 %0, t; }"
        : "=r"(a) : "l"(p));
    return a;
}
static __device__ __forceinline__ uint32_t sw128(uint32_t o) {
    return o ^ ((o >> 3) & 0x70);
}
static __device__ __forceinline__ void ldsm4(uint32_t& r0, uint32_t& r1,
                                             uint32_t& r2, uint32_t& r3, uint32_t a) {
    asm volatile("ldmatrix.sync.aligned.m8n8.x4.shared.b16 {%0,%1,%2,%3}, [%4];"
                 : "=r"(r0), "=r"(r1), "=r"(r2), "=r"(r3) : "r"(a));
}
static __device__ __forceinline__ void mma16816(float& c0, float& c1, float& c2, float& c3,
                                                uint32_t a0, uint32_t a1, uint32_t a2, uint32_t a3,
                                                uint32_t b0, uint32_t b1) {
    asm volatile(
        "mma.sync.aligned.m16n8k16.row.col.f32.bf16.bf16.f32 "
        "{%0,%1,%2,%3}, {%4,%5,%6,%7}, {%8,%9}, {%0,%1,%2,%3};"
        : "+f"(c0), "+f"(c1), "+f"(c2), "+f"(c3)
        : "r"(a0), "r"(a1), "r"(a2), "r"(a3), "r"(b0), "r"(b1));
}
static __device__ __forceinline__ void cpa16(uint32_t s, const void* g) {
    asm volatile("cp.async.cg.shared.global [%0], [%1], 16;" :: "r"(s), "l"(g));
}
static __device__ __forceinline__ void cpa_commit() {
    asm volatile("cp.async.commit_group;");
}
// fp32x4 -> hi/lo bf16x4 split, packed as uint2 each
static __device__ __forceinline__ void split4(float4 v, uint2& hi, uint2& lo) {
    __nv_bfloat162 h01 = __floats2bfloat162_rn(v.x, v.y);
    __nv_bfloat162 h23 = __floats2bfloat162_rn(v.z, v.w);
    float r0 = v.x - __bfloat162float(h01.x);
    float r1 = v.y - __bfloat162float(h01.y);
    float r2 = v.z - __bfloat162float(h23.x);
    float r3 = v.w - __bfloat162float(h23.y);
    __nv_bfloat162 l01 = __floats2bfloat162_rn(r0, r1);
    __nv_bfloat162 l23 = __floats2bfloat162_rn(r2, r3);
    hi.x = *reinterpret_cast<uint32_t*>(&h01);
    hi.y = *reinterpret_cast<uint32_t*>(&h23);
    lo.x = *reinterpret_cast<uint32_t*>(&l01);
    lo.y = *reinterpret_cast<uint32_t*>(&l23);
}

// ------------------------------ prep kernels --------------------------------
__global__ void prep_split(const float* __restrict__ src,
                           uint16_t* __restrict__ hi, uint16_t* __restrict__ lo,
                           size_t n4)
{
    uint2* h2 = reinterpret_cast<uint2*>(hi);
    uint2* l2 = reinterpret_cast<uint2*>(lo);
    for (size_t i = blockIdx.x * blockDim.x + threadIdx.x; i < n4;
         i += (size_t)gridDim.x * blockDim.x) {
        uint2 hu, lu;
        split4(reinterpret_cast<const float4*>(src)[i], hu, lu);
        h2[i] = hu; l2[i] = lu;
    }
}
__global__ void prep_scale_split(const float* __restrict__ U,
                                 const float* __restrict__ S,
                                 const float* __restrict__ eps,
                                 uint16_t* __restrict__ hi, uint16_t* __restrict__ lo,
                                 size_t n4, int rq)   // rq = r/4
{
    uint2* h2 = reinterpret_cast<uint2*>(hi);
    uint2* l2 = reinterpret_cast<uint2*>(lo);
    for (size_t i = blockIdx.x * blockDim.x + threadIdx.x; i < n4;
         i += (size_t)gridDim.x * blockDim.x) {
        size_t c4 = i % rq;
        float4 v = reinterpret_cast<const float4*>(U)[i];
        float4 sv = reinterpret_cast<const float4*>(S)[c4];
        float4 ev = reinterpret_cast<const float4*>(eps)[c4];
        v.x *= (sv.x + ev.x); v.y *= (sv.y + ev.y);
        v.z *= (sv.z + ev.z); v.w *= (sv.w + ev.w);
        uint2 hu, lu;
        split4(v, hu, lu);
        h2[i] = hu; l2[i] = lu;
    }
}
// Vt [r][dIn] -> vh/vl [dIn][r] (transpose + split)
__global__ void prep_transpose_split(const float* __restrict__ Vt,
                                     uint16_t* __restrict__ hi, uint16_t* __restrict__ lo,
                                     int R, int dIn)
{
    __shared__ float tile[32][33];
    const int tx = threadIdx.x, ty = threadIdx.y;  // 32 x 8
    const int k0 = blockIdx.y * 32, n0 = blockIdx.x * 32;
    #pragma unroll
    for (int j = 0; j < 4; j++)
        tile[ty + j * 8][tx] = Vt[(size_t)(k0 + ty + j * 8) * dIn + n0 + tx];
    __syncthreads();
    #pragma unroll
    for (int j = 0; j < 4; j++) {
        float v = tile[tx][ty + j * 8];
        __nv_bfloat16 h = __float2bfloat16_rn(v);
        __nv_bfloat16 l = __float2bfloat16_rn(v - __bfloat162float(h));
        size_t o = (size_t)(n0 + ty + j * 8) * R + k0 + tx;
        hi[o] = *reinterpret_cast<uint16_t*>(&h);
        lo[o] = *reinterpret_cast<uint16_t*>(&l);
    }
}

// ------------------------------ GEMM core -----------------------------------
// CTA tile 128(m) x 256(n), Kc=64. 8 warps (2m x 4n), warp tile 64x64.
// smem/stage: AH 16K | AL 16K | BH 32K | BL 32K = 96KB; 2 stages = 192KB.
#define KC 64
#define T_AH 0
#define T_AL 16384
#define T_BH 32768
#define T_BL 65536
#define STAGE 98304
#define SMEM_BYTES (2 * STAGE)

template<int EPI>   // 0: split-bf16 output (GEMM1), 1: fp32 + bias (GEMM2)
__global__ __launch_bounds__(256, 1)
void gemm_bf16x3(const uint16_t* __restrict__ Agh, const uint16_t* __restrict__ Agl,
                 const uint16_t* __restrict__ Bgh, const uint16_t* __restrict__ Bgl,
                 float* __restrict__ Yout, const float* __restrict__ bias,
                 uint16_t* __restrict__ Wh, uint16_t* __restrict__ Wl,
                 int M, int N, int K)
{
    extern __shared__ char smem[];
    const uint32_t sb = smem_u32(smem);

    const int tid = threadIdx.x;
    const int wid = tid >> 5, lane = tid & 31;
    const int m0 = blockIdx.y * 128;
    const int n0 = blockIdx.x * 256;
    const int mw = (wid & 1) * 64;
    const int nw = (wid >> 1) * 64;

    const uint32_t rowA = mw + (lane & 7) + ((lane >> 3) & 1) * 8;
    const uint32_t colA = ((lane >> 4) & 1) * 16;
    const uint32_t rowB = nw + (lane & 7) + ((lane >> 4) & 1) * 8;
    const uint32_t colB = ((lane >> 3) & 1) * 16;

    float acc[4][8][4];
    #pragma unroll
    for (int i = 0; i < 4; i++)
        #pragma unroll
        for (int j = 0; j < 8; j++)
            #pragma unroll
            for (int q = 0; q < 4; q++) acc[i][j][q] = 0.f;

    const int KI = K / KC;

    // stage loader: 24 cp.async x 16B per thread
    auto ISSUE = [&](int stg, int kt) {
        const uint32_t base = sb + (uint32_t)stg * STAGE;
        const int k0 = kt * KC;
        #pragma unroll
        for (int i = 0; i < 4; i++) {                  // A: 1024 chunks / half
            int c = tid + i * 256, row = c >> 3, q = c & 7;
            uint32_t off = sw128((uint32_t)(row * 128 + q * 16));
            const size_t go = (size_t)(m0 + row) * K + k0 + q * 8;
            cpa16(base + T_AH + off, Agh + go);
            cpa16(base + T_AL + off, Agl + go);
        }
        #pragma unroll
        for (int i = 0; i < 8; i++) {                  // B: 2048 chunks / half
            int c = tid + i * 256, row = c >> 3, q = c & 7;
            uint32_t off = sw128((uint32_t)(row * 128 + q * 16));
            const size_t go = (size_t)(n0 + row) * K + k0 + q * 8;
            cpa16(base + T_BH + off, Bgh + go);
            cpa16(base + T_BL + off, Bgl + go);
        }
        cpa_commit();
    };

    ISSUE(0, 0);

    for (int kt = 0; kt < KI; kt++) {
        const bool hasNext = (kt + 1 < KI);
        if (hasNext) ISSUE((kt + 1) & 1, kt + 1);
        if (hasNext) asm volatile("cp.async.wait_group 1;" ::: "memory");
        else         asm volatile("cp.async.wait_group 0;" ::: "memory");
        __syncthreads();

        const uint32_t Ah = sb + (uint32_t)(kt & 1) * STAGE + T_AH;
        const uint32_t Al = Ah + (T_AL - T_AH);
        const uint32_t Bh = sb + (uint32_t)(kt & 1) * STAGE + T_BH;
        const uint32_t Bl = Bh + (T_BL - T_BH);

        #pragma unroll
        for (int kk = 0; kk < 4; kk++) {
            uint32_t ah[4][4], al[4][4], bh[4][4], bl[4][4];
            #pragma unroll
            for (int mi = 0; mi < 4; mi++) {
                uint32_t off = sw128((rowA + mi * 16) * 128 + kk * 32 + colA);
                ldsm4(ah[mi][0], ah[mi][1], ah[mi][2], ah[mi][3], Ah + off);
                ldsm4(al[mi][0], al[mi][1], al[mi][2], al[mi][3], Al + off);
            }
            #pragma unroll
            for (int p = 0; p < 4; p++) {
                uint32_t off = sw128((rowB + p * 16) * 128 + kk * 32 + colB);
                ldsm4(bh[p][0], bh[p][1], bh[p][2], bh[p][3], Bh + off);
                ldsm4(bl[p][0], bl[p][1], bl[p][2], bl[p][3], Bl + off);
            }
            #pragma unroll
            for (int mi = 0; mi < 4; mi++) {
                #pragma unroll
                for (int ni = 0; ni < 8; ni++) {
                    uint32_t vb0 = bh[ni >> 1][(ni & 1) * 2];
                    uint32_t vb1 = bh[ni >> 1][(ni & 1) * 2 + 1];
                    uint32_t wb0 = bl[ni >> 1][(ni & 1) * 2];
                    uint32_t wb1 = bl[ni >> 1][(ni & 1) * 2 + 1];
                    float* c = acc[mi][ni];
                    mma16816(c[0], c[1], c[2], c[3],
                             ah[mi][0], ah[mi][1], ah[mi][2], ah[mi][3], vb0, vb1);
                    mma16816(c[0], c[1], c[2], c[3],
                             ah[mi][0], ah[mi][1], ah[mi][2], ah[mi][3], wb0, wb1);
                    mma16816(c[0], c[1], c[2], c[3],
                             al[mi][0], al[mi][1], al[mi][2], al[mi][3], vb0, vb1);
                }
            }
        }
        __syncthreads();
    }

    // ------------------------------ epilogue ---------------------------------
    const int erow = lane >> 2;
    const int ecol = (lane & 3) * 2;
    if (EPI == 1) {
        #pragma unroll
        for (int ni = 0; ni < 8; ni++) {
            int n = n0 + nw + ni * 8 + ecol;
            float2 bv = *reinterpret_cast<const float2*>(bias + n);
            #pragma unroll
            for (int mi = 0; mi < 4; mi++) {
                int m = m0 + mw + mi * 16 + erow;
                float* c = acc[mi][ni];
                *reinterpret_cast<float2*>(Yout + (size_t)m * N + n) =
                    make_float2(c[0] + bv.x, c[1] + bv.y);
                *reinterpret_cast<float2*>(Yout + (size_t)(m + 8) * N + n) =
                    make_float2(c[2] + bv.x, c[3] + bv.y);
            }
        }
    } else {
        #pragma unroll
        for (int ni = 0; ni < 8; ni++) {
            int n = n0 + nw + ni * 8 + ecol;
            #pragma unroll
            for (int mi = 0; mi < 4; mi++) {
                int m = m0 + mw + mi * 16 + erow;
                float* c = acc[mi][ni];
                #pragma unroll
                for (int half = 0; half < 2; half++) {
                    float v0 = c[half * 2], v1 = c[half * 2 + 1];
                    __nv_bfloat162 h = __floats2bfloat162_rn(v0, v1);
                    __nv_bfloat162 l = __floats2bfloat162_rn(
                        v0 - __bfloat162float(h.x), v1 - __bfloat162float(h.y));
                    size_t o = (size_t)(m + half * 8) * N + n;
                    *reinterpret_cast<uint32_t*>(Wh + o) = *reinterpret_cast<uint32_t*>(&h);
                    *reinterpret_cast<uint32_t*>(Wl + o) = *reinterpret_cast<uint32_t*>(&l);
                }
            }
        }
    }
}

// =============================================================================
// Entry. Inputs: x, U, S, Vt, epsilon, bias
// =============================================================================
extern "C" void kernel_launch(void* const* d_in, const int* in_sizes, int n_in,
                              void* d_out, int out_size)
{
    const float* x    = (const float*)d_in[0];
    const float* U    = (const float*)d_in[1];
    const float* S    = (const float*)d_in[2];
    const float* Vt   = (const float*)d_in[3];
    const float* eps  = (const float*)d_in[4];
    const float* bias = (const float*)d_in[5];
    float* y = (float*)d_out;

    const int r    = in_sizes[2];          // 4096
    const int dIn  = in_sizes[3] / r;      // 4096
    const int dOut = in_sizes[1] / r;      // 4096
    const int M    = in_sizes[0] / dIn;    // 8192

    static bool attr_done = false;
    if (!attr_done) {
        cudaFuncSetAttribute(gemm_bf16x3<0>, cudaFuncAttributeMaxDynamicSharedMemorySize, SMEM_BYTES);
        cudaFuncSetAttribute(gemm_bf16x3<1>, cudaFuncAttributeMaxDynamicSharedMemorySize, SMEM_BYTES);
        attr_done = true;
    }

    // device-global scratch (extern access via symbols through launch params)
    uint16_t *xh, *xl, *uh, *ul, *vh, *vl, *wh, *wl;
    cudaGetSymbolAddress((void**)&xh, g_xh);
    cudaGetSymbolAddress((void**)&xl, g_xl);
    cudaGetSymbolAddress((void**)&uh, g_uh);
    cudaGetSymbolAddress((void**)&ul, g_ul);
    cudaGetSymbolAddress((void**)&vh, g_vh);
    cudaGetSymbolAddress((void**)&vl, g_vl);
    cudaGetSymbolAddress((void**)&wh, g_wh);
    cudaGetSymbolAddress((void**)&wl, g_wl);

    // prep
    prep_split<<<4096, 256>>>(x, xh, xl, (size_t)M * dIn / 4);
    prep_scale_split<<<4096, 256>>>(U, S, eps, uh, ul, (size_t)dOut * r / 4, r / 4);
    {
        dim3 grid(dIn / 32, r / 32), blk(32, 8);
        prep_transpose_split<<<grid, blk>>>(Vt, vh, vl, r, dIn);
    }
    // GEMM1: w[dOut, dIn] = u @ v^T (split output)
    {
        dim3 grid(dIn / 256, dOut / 128);
        gemm_bf16x3<0><<<grid, 256, SMEM_BYTES>>>(uh, ul, vh, vl,
                                                  nullptr, nullptr, wh, wl,
                                                  dOut, dIn, r);
    }
    // GEMM2: y[M, dOut] = x @ w^T + bias
    {
        dim3 grid(dOut / 256, M / 128);
        gemm_bf16x3<1><<<grid, 256, SMEM_BYTES>>>(xh, xl, wh, wl,
                                                  y, bias, nullptr, nullptr,
                                                  M, dOut, dIn);
    }
}